// round 14
// baseline (speedup 1.0000x reference)
#include <cuda_runtime.h>
#include <cuda_bf16.h>

// ---------------------------------------------------------------------------
// SageConv: out = relu([x@Wl + bl | (scatter_sum(val*x[col] -> row))@Wn + bn])
// N=100000 nodes, E=1.6M edges, D_IN=D_OUT=128.
//
// Round 14: fused GEMM rewritten with K-PAIR f32x2 packing (zero splat MOVs):
//   acc[r][c] = {sum over even k, sum over odd k}; a-operand = consecutive
//   tile floats; b-operand = consecutive floats of a TRANSPOSED W in smem
//   (pitch 130 for alignment + bank spread). Horizontal add at epilogue.
// Build/pull kernels = R11-proven forms (batching reverted; hist atomics are
// REDG and were never latency-bound). g_total reset in head zero kernel.
// ---------------------------------------------------------------------------

#define NN 100000
#define EE 1600000
#define D 128

__device__ __align__(16) float g_agg[NN * D];
__device__ int g_deg[NN];
__device__ int g_off[NN + 1];
__device__ int g_cur[NN];
__device__ int g_total;
__device__ __align__(8) unsigned long long g_csr[EE];  // hi32=val, lo32=col

// ---------------------------------------------------------------------------
__global__ void k_zero_deg(int n) {
    if (blockIdx.x == 0 && threadIdx.x == 0) g_total = 0;
    for (int i = blockIdx.x * blockDim.x + threadIdx.x; i < n;
         i += gridDim.x * blockDim.x)
        g_deg[i] = 0;
}

__global__ void k_hist(const int* __restrict__ erow, int E) {
    for (int e = blockIdx.x * blockDim.x + threadIdx.x; e < E;
         e += gridDim.x * blockDim.x)
        atomicAdd(&g_deg[__ldg(erow + e)], 1);
}

// block reduce -> 1 atomicAdd base claim -> block scan -> offsets+cursors
__global__ void k_alloc(int n) {
    __shared__ int s[256];
    __shared__ int sbase;
    int t = threadIdx.x;
    int i = blockIdx.x * 256 + t;
    int dg = (i < n) ? g_deg[i] : 0;
    s[t] = dg;
    __syncthreads();
    for (int d = 1; d < 256; d <<= 1) {
        int v = (t >= d) ? s[t - d] : 0;
        __syncthreads();
        s[t] += v;
        __syncthreads();
    }
    if (t == 255) sbase = atomicAdd(&g_total, s[255]);
    __syncthreads();
    if (i < n) {
        int off = sbase + s[t] - dg;
        g_off[i] = off;
        g_cur[i] = off;
    }
}

__global__ void k_bin(const int* __restrict__ erow,
                      const int* __restrict__ ecol,
                      const float* __restrict__ eval_, int E) {
    for (int e = blockIdx.x * blockDim.x + threadIdx.x; e < E;
         e += gridDim.x * blockDim.x) {
        int r = __ldg(erow + e);
        int c = __ldg(ecol + e);
        float v = __ldg(eval_ + e);
        int pos = atomicAdd(&g_cur[r], 1);
        g_csr[pos] = ((unsigned long long)__float_as_uint(v) << 32) | (unsigned)c;
    }
}

// ---------------------------------------------------------------------------
// Pull-style SpMM: one warp per row; 4 independent gathers in flight.
__global__ void __launch_bounds__(256)
k_pull(const float4* __restrict__ x4, int n) {
    const int lane = threadIdx.x & 31;
    const int gwarp = (blockIdx.x * blockDim.x + threadIdx.x) >> 5;
    const int nwarps = (gridDim.x * blockDim.x) >> 5;

    for (int r = gwarp; r < n; r += nwarps) {
        const int beg = __ldg(g_off + r);
        const int end = beg + __ldg(g_deg + r);
        float4 acc = make_float4(0.f, 0.f, 0.f, 0.f);

        int j = beg;
        for (; j + 4 <= end; j += 4) {
            unsigned long long p0 = __ldg(g_csr + j);
            unsigned long long p1 = __ldg(g_csr + j + 1);
            unsigned long long p2 = __ldg(g_csr + j + 2);
            unsigned long long p3 = __ldg(g_csr + j + 3);
            float4 a = __ldg(x4 + (size_t)(unsigned)p0 * 32 + lane);
            float4 b = __ldg(x4 + (size_t)(unsigned)p1 * 32 + lane);
            float4 c = __ldg(x4 + (size_t)(unsigned)p2 * 32 + lane);
            float4 dd = __ldg(x4 + (size_t)(unsigned)p3 * 32 + lane);
            float v0 = __uint_as_float((unsigned)(p0 >> 32));
            float v1 = __uint_as_float((unsigned)(p1 >> 32));
            float v2 = __uint_as_float((unsigned)(p2 >> 32));
            float v3 = __uint_as_float((unsigned)(p3 >> 32));
            acc.x += v0 * a.x; acc.y += v0 * a.y; acc.z += v0 * a.z; acc.w += v0 * a.w;
            acc.x += v1 * b.x; acc.y += v1 * b.y; acc.z += v1 * b.z; acc.w += v1 * b.w;
            acc.x += v2 * c.x; acc.y += v2 * c.y; acc.z += v2 * c.z; acc.w += v2 * c.w;
            acc.x += v3 * dd.x; acc.y += v3 * dd.y; acc.z += v3 * dd.z; acc.w += v3 * dd.w;
        }
        for (; j < end; j++) {
            unsigned long long p = __ldg(g_csr + j);
            float4 a = __ldg(x4 + (size_t)(unsigned)p * 32 + lane);
            float v = __uint_as_float((unsigned)(p >> 32));
            acc.x += v * a.x; acc.y += v * a.y; acc.z += v * a.z; acc.w += v * a.w;
        }
        reinterpret_cast<float4*>(g_agg)[(size_t)r * 32 + lane] = acc;
    }
}

// ---------------------------------------------------------------------------
// Packed fp32x2 FMA (sm_103a): d = a * b + d
#define FMA2(d, a, b) \
    asm("fma.rn.f32x2 %0, %1, %2, %0;" : "+l"(d) : "l"(a), "l"(b))

__device__ __forceinline__ float2 unpack2(unsigned long long p) {
    float2 r;
    asm("mov.b64 {%0, %1}, %2;" : "=f"(r.x), "=f"(r.y) : "l"(p));
    return r;
}

// Shared layout (floats):
//   sWt: transposed weights [2][128 cols][pitch 130] : Wt[half][c][k]
//   sT : tile [2][32 rows][128]  (x rows | agg rows)
#define WT_PITCH 130
#define TMR 32
#define OFF_T (2 * D * WT_PITCH)                 // 33280 floats
#define SMEM_FLOATS (OFF_T + 2 * TMR * D)        // +8192 = 41472 floats
#define SMEM_BYTES (SMEM_FLOATS * 4)             // 165888 B

// Tile = 32 rows. Warps 0-3: local half (x, Wl); warps 4-7: neigh (agg, Wn).
// Warp covers rows (w&3)*8 .. +8. Lane covers cols {lane, lane+32, +64, +96}.
// K-pair packing: acc[r][c] = {even-k partial, odd-k partial}; both FFMA2
// operands come packed straight from smem loads -> zero MOV splats.
__global__ void __launch_bounds__(256)
fused_kernel(const float* __restrict__ x,
             const float* __restrict__ Wl,
             const float* __restrict__ bl,
             const float* __restrict__ Wn,
             const float* __restrict__ bn,
             float* __restrict__ out,
             int n) {
    extern __shared__ float sm[];
    float* sWt = sm;            // transposed weights
    float* sT = sm + OFF_T;     // tiles

    const int tid = threadIdx.x;
    const int lane = tid & 31;
    const int w = tid >> 5;
    const int half = w >> 2;          // 0=local, 1=neigh
    const int r0 = (w & 3) * 8;

    // Transpose both W matrices into smem: sWt[half][c][k] = W[k*128+c]
    for (int u = tid; u < D * D; u += 256) {
        int k = u >> 7, c = u & 127;
        sWt[c * WT_PITCH + k] = __ldg(Wl + u);
        sWt[D * WT_PITCH + c * WT_PITCH + k] = __ldg(Wn + u);
    }

    const float* Wt = sWt + half * (D * WT_PITCH);
    const float* bias = half ? bn : bl;
    float bb[4];
#pragma unroll
    for (int c = 0; c < 4; c++) bb[c] = __ldg(bias + lane + c * 32);

    const float4* x4 = reinterpret_cast<const float4*>(x);
    const float4* a4 = reinterpret_cast<const float4*>(g_agg);

    const int ntiles = (n + TMR - 1) / TMR;
    __syncthreads();

    for (int t = blockIdx.x; t < ntiles; t += gridDim.x) {
        const int row0 = t * TMR;
        __syncthreads();
        // sT rows 0..31 = x[row0..), rows 32..63 = agg[same rows)
        {
            float4* sT4 = reinterpret_cast<float4*>(sT);
            float4 z = make_float4(0.f, 0.f, 0.f, 0.f);
            for (int i = tid; i < TMR * 32; i += 256) {
                int r = i >> 5, kk = i & 31;
                int gr = row0 + r;
                float4 vx = z, va = z;
                if (gr < n) {
                    vx = x4[(size_t)gr * 32 + kk];
                    va = a4[(size_t)gr * 32 + kk];
                }
                sT4[i] = vx;
                sT4[TMR * 32 + i] = va;
            }
        }
        __syncthreads();

        const float* Abase = sT + half * (TMR * D) + r0 * D;

        unsigned long long acc[8][4];
#pragma unroll
        for (int r = 0; r < 8; r++)
#pragma unroll
            for (int c = 0; c < 4; c++) acc[r][c] = 0ull;

        for (int k = 0; k < D; k += 4) {
            // A: 8 rows x 4 k-values; 16B loads, broadcast (warp-uniform addr)
            ulonglong2 av[8];
#pragma unroll
            for (int r = 0; r < 8; r++)
                av[r] = *reinterpret_cast<const ulonglong2*>(Abase + r * D + k);
            // W: 4 cols x 2 k-pairs via 8B loads (pitch 130: 8B-aligned,
            // bank = (2*lane + k) % 32 -> <=2-way conflicts)
            unsigned long long wv[4][2];
#pragma unroll
            for (int c = 0; c < 4; c++) {
                const float* wp = Wt + (lane + c * 32) * WT_PITCH + k;
                wv[c][0] = *reinterpret_cast<const unsigned long long*>(wp);
                wv[c][1] = *reinterpret_cast<const unsigned long long*>(wp + 2);
            }
#pragma unroll
            for (int r = 0; r < 8; r++)
#pragma unroll
                for (int c = 0; c < 4; c++) {
                    FMA2(acc[r][c], av[r].x, wv[c][0]);
                    FMA2(acc[r][c], av[r].y, wv[c][1]);
                }
        }

        // Epilogue: horizontal add, bias, relu; coalesced 4B stores
#pragma unroll
        for (int r = 0; r < 8; r++) {
            int gr = row0 + r0 + r;
            if (gr < n) {
                float* op = out + (size_t)gr * 256 + half * D + lane;
#pragma unroll
                for (int c = 0; c < 4; c++) {
                    float2 p = unpack2(acc[r][c]);
                    __stcs(op + c * 32, fmaxf(p.x + p.y + bb[c], 0.f));
                }
            }
        }
    }
}

// ---------------------------------------------------------------------------
extern "C" void kernel_launch(void* const* d_in, const int* in_sizes, int n_in,
                              void* d_out, int out_size) {
    const float* x  = (const float*)d_in[0];
    const int* erow = (const int*)d_in[1];
    const int* ecol = (const int*)d_in[2];
    const float* ev = (const float*)d_in[3];
    const float* Wl = (const float*)d_in[4];
    const float* bl = (const float*)d_in[5];
    const float* Wn = (const float*)d_in[6];
    const float* bn = (const float*)d_in[7];

    const int n = in_sizes[0] / D;   // nodes (100000)
    const int E = in_sizes[1];       // edges (1600000)
    const int nb = (n + 255) / 256;

    // CSR build
    k_zero_deg<<<256, 256>>>(n);
    k_hist<<<1024, 256>>>(erow, E);
    k_alloc<<<nb, 256>>>(n);
    k_bin<<<1024, 256>>>(erow, ecol, ev, E);

    // Pull-style SpMM
    k_pull<<<2048, 256>>>(reinterpret_cast<const float4*>(x), n);

    // Fused dual-GEMM + bias + relu + concat (k-pair packed, zero splats)
    cudaFuncSetAttribute(fused_kernel,
                         cudaFuncAttributeMaxDynamicSharedMemorySize, SMEM_BYTES);
    fused_kernel<<<148, 256, SMEM_BYTES>>>(x, Wl, bl, Wn, bn, (float*)d_out, n);
}